// round 9
// baseline (speedup 1.0000x reference)
#include <cuda_runtime.h>

// Conditional encoding: 2-layer LSTM (B=1024, T=256, D=50, H=64) + MLP head.
// x@Wih^T+bias precomputed per vocab entry; table layout tab[v][ch][{i,f,g,o}]
// (combine fetches all 4 gate-x with ONE LDG.128).
// Recurrence: balanced grid 292 = 148 CTAs x 4 rows + 144 CTAs x 3 rows,
// 512 threads/CTA, 2 CTAs/SM -> 8 warps/SMSP. Thread = gate PAIR x k-quarter
// (32 weight regs), partials via STS.64, combine per (row,channel).

#define BB   1024
#define TT   256
#define DD   50
#define HH   64
#define GG   256   // 4*H
#define VV   32004
#define NTHR 512
#define HP   72    // padded h row stride
#define VB   1001  // ceil(32004/32)

typedef unsigned long long u64;

__device__ float g_tab0[(long)VV * GG];   // layer-1 table, [v][ch][4] = i,f,g,o
__device__ float g_tab1[(long)VV * GG];   // layer-2 table

__device__ __forceinline__ u64 pk2(float a, float b) {
    u64 r; asm("mov.b64 %0, {%1, %2};" : "=l"(r) : "f"(a), "f"(b)); return r;
}
__device__ __forceinline__ u64 ffma2(u64 a, u64 b, u64 c) {
    u64 d; asm("fma.rn.f32x2 %0, %1, %2, %3;" : "=l"(d) : "l"(a), "l"(b), "l"(c)); return d;
}
__device__ __forceinline__ float pairsum(u64 a) {
    float x, y; asm("mov.b64 {%0, %1}, %2;" : "=f"(x), "=f"(y) : "l"(a)); return x + y;
}
__device__ __forceinline__ float tanha(float x) {
    float y; asm("tanh.approx.f32 %0, %1;" : "=f"(y) : "f"(x)); return y;
}
__device__ __forceinline__ float siga(float x) {
    return fmaf(0.5f, tanha(0.5f * x), 0.5f);
}

// staging remap: gate g -> bit7 = type>=2, bits[6:1] = channel, bit0 = type&1.
__device__ __forceinline__ int remap(int g) {
    return ((g >> 7) << 7) | ((g & 63) << 1) | ((g >> 6) & 1);
}

// ---------------- precompute: tab[v][ch][4] = {i,f,g,o} preacts ----------------
__global__ void __launch_bounds__(256) precompute_kernel(
    const float* __restrict__ emb,
    const float* __restrict__ WihA, const float* __restrict__ biA, const float* __restrict__ bhA,
    const float* __restrict__ WihB, const float* __restrict__ biB, const float* __restrict__ bhB)
{
    const int layer = blockIdx.x >= VB;
    const int vb    = layer ? blockIdx.x - VB : blockIdx.x;
    const float* Wih = layer ? WihB : WihA;
    const float* bi  = layer ? biB  : biA;
    const float* bh  = layer ? bhB  : bhA;
    float* tab = layer ? g_tab1 : g_tab0;

    __shared__ float xs[32][DD];
    __shared__ __align__(8) float wsT[25][GG];
    __shared__ __align__(8) float bsh[GG];

    const int tid = threadIdx.x;
    const int v0  = vb * 32;
    const int rm  = remap(tid);

    for (int idx = tid; idx < 32 * DD; idx += 256) {
        int v = idx / DD, k = idx - v * DD;
        int vg = v0 + v;
        xs[v][k] = (vg < VV) ? emb[(long)vg * DD + k] : 0.f;
    }
    bsh[rm] = bi[tid] + bh[tid];
    __syncthreads();

    const int gg = tid & 31;
    const int vq = tid >> 5;
    const int off0 = 2 * gg, off1 = 128 + 2 * gg;
    const int off2 = 2 * (gg + 32), off3 = 128 + 2 * (gg + 32);

    u64 acc[4][4];
    {
        u64 b0 = *(const u64*)&bsh[off0], b1 = *(const u64*)&bsh[off1];
        u64 b2 = *(const u64*)&bsh[off2], b3 = *(const u64*)&bsh[off3];
        #pragma unroll
        for (int v = 0; v < 4; ++v) {
            acc[v][0] = b0; acc[v][1] = b1; acc[v][2] = b2; acc[v][3] = b3;
        }
    }

    for (int kc = 0; kc < 2; ++kc) {
        __syncthreads();
        {
            const float* wp = Wih + (long)tid * DD + kc * 25;
            #pragma unroll
            for (int k = 0; k < 25; ++k) wsT[k][rm] = wp[k];
        }
        __syncthreads();
        #pragma unroll
        for (int k = 0; k < 25; ++k) {
            u64 w0 = *(const u64*)&wsT[k][off0];
            u64 w1 = *(const u64*)&wsT[k][off1];
            u64 w2 = *(const u64*)&wsT[k][off2];
            u64 w3 = *(const u64*)&wsT[k][off3];
            #pragma unroll
            for (int v = 0; v < 4; ++v) {
                float xv = xs[vq * 4 + v][kc * 25 + k];
                u64 xp = pk2(xv, xv);
                acc[v][0] = ffma2(w0, xp, acc[v][0]);
                acc[v][1] = ffma2(w1, xp, acc[v][1]);
                acc[v][2] = ffma2(w2, xp, acc[v][2]);
                acc[v][3] = ffma2(w3, xp, acc[v][3]);
            }
        }
    }

    #pragma unroll
    for (int v = 0; v < 4; ++v) {
        int vg = v0 + vq * 4 + v;
        if (vg < VV) {
            float* base = tab + (long)vg * GG;
            *(u64*)(base + 4 * gg)            = acc[v][0];
            *(u64*)(base + 4 * gg + 2)        = acc[v][1];
            *(u64*)(base + 4 * (gg + 32))     = acc[v][2];
            *(u64*)(base + 4 * (gg + 32) + 2) = acc[v][3];
        }
    }
}

// ---------------- recurrent core (templated on rows per CTA) ----------------
template <int BT>
__device__ __forceinline__ void run_lstm(
    int b0, int tid,
    const int*   __restrict__ s1,   const int*   __restrict__ s2,
    const int*   __restrict__ len1, const int*   __restrict__ len2,
    const float* __restrict__ Whh1, const float* __restrict__ Whh2,
    const float* __restrict__ Wl1,  const float* __restrict__ bl1,
    const float* __restrict__ Wl2,  const float* __restrict__ bl2,
    float* __restrict__ out,
    int   (*toksh)[TT],
    float (*hA)[HP], float (*hB)[HP],
    float (*pre4)[4][GG],
    float (*ghh)[HH], float (*l1sh)[128])
{
    const int P  = tid & 127;            // gate pair: gates 2P, 2P+1
    const int kq = tid >> 7;             // k quarter: h[16kq .. 16kq+15]
    const int cr = tid >> 6;             // combine row
    const int ch = tid & 63;             // combine channel
    const bool comb = (tid < BT * 64);

    u64    wreg[16];                     // [gi*8+j]: gate 2P+gi, k-pair j
    float4 gx4, pf4;
    float  cmy = 0.f, mgh = 0.f, mgc = 0.f;
    int    glmy = -1;

    for (int phase = 0; phase < 2; ++phase) {
        const int*   sent = phase ? s2   : s1;
        const int*   slen = phase ? len2 : len1;
        const float* Whh  = phase ? Whh2 : Whh1;
        const float* tab  = phase ? g_tab1 : g_tab0;

        #pragma unroll
        for (int gi = 0; gi < 2; ++gi) {
            const float4* wp = (const float4*)(Whh + (long)(2 * P + gi) * HH + 16 * kq);
            #pragma unroll
            for (int j = 0; j < 4; ++j) {
                float4 w = wp[j];
                wreg[gi * 8 + 2 * j]     = pk2(w.x, w.y);
                wreg[gi * 8 + 2 * j + 1] = pk2(w.z, w.w);
            }
        }
        for (int idx = tid; idx < BT * TT; idx += NTHR) {
            int r = idx >> 8, t = idx & 255;
            toksh[r][t] = sent[(b0 + r) * TT + t];
        }
        if (comb) {
            glmy = slen[(b0 + cr) * HH + ch];
            cmy  = (phase == 0) ? 0.f : mgc;
            hA[cr][ch] = (phase == 0) ? 0.f : mgh;
        }
        __syncthreads();

        if (comb)
            gx4 = __ldg((const float4*)&tab[(long)toksh[cr][0] * GG + 4 * ch]);

        #define LSTEP(HRD, HWR, TCUR, TNX)                                     \
        {                                                                      \
            if (comb)                                                          \
                pf4 = __ldg((const float4*)&tab[(long)toksh[cr][(TNX)] * GG + 4 * ch]); \
            _Pragma("unroll")                                                  \
            for (int r = 0; r < BT; ++r) {                                     \
                const ulonglong2* hp = (const ulonglong2*)&HRD[r][16 * kq];    \
                ulonglong2 h0 = hp[0], h1 = hp[1], h2 = hp[2], h3 = hp[3];     \
                u64 a0 = 0ULL, a1 = 0ULL;                                      \
                a0 = ffma2(wreg[0], h0.x, a0); a1 = ffma2(wreg[8],  h0.x, a1); \
                a0 = ffma2(wreg[1], h0.y, a0); a1 = ffma2(wreg[9],  h0.y, a1); \
                a0 = ffma2(wreg[2], h1.x, a0); a1 = ffma2(wreg[10], h1.x, a1); \
                a0 = ffma2(wreg[3], h1.y, a0); a1 = ffma2(wreg[11], h1.y, a1); \
                a0 = ffma2(wreg[4], h2.x, a0); a1 = ffma2(wreg[12], h2.x, a1); \
                a0 = ffma2(wreg[5], h2.y, a0); a1 = ffma2(wreg[13], h2.y, a1); \
                a0 = ffma2(wreg[6], h3.x, a0); a1 = ffma2(wreg[14], h3.x, a1); \
                a0 = ffma2(wreg[7], h3.y, a0); a1 = ffma2(wreg[15], h3.y, a1); \
                float2 s;                                                      \
                s.x = pairsum(a0); s.y = pairsum(a1);                          \
                *(float2*)&pre4[kq][r][2 * P] = s;                             \
            }                                                                  \
            __syncthreads();                                                   \
            if (comb) {                                                        \
                float iv = ((pre4[0][cr][ch] + pre4[1][cr][ch])                \
                          + (pre4[2][cr][ch] + pre4[3][cr][ch])) + gx4.x;      \
                float fv = ((pre4[0][cr][64 + ch] + pre4[1][cr][64 + ch])      \
                          + (pre4[2][cr][64 + ch] + pre4[3][cr][64 + ch])) + gx4.y; \
                float gv = ((pre4[0][cr][128 + ch] + pre4[1][cr][128 + ch])    \
                          + (pre4[2][cr][128 + ch] + pre4[3][cr][128 + ch])) + gx4.z; \
                float ov = ((pre4[0][cr][192 + ch] + pre4[1][cr][192 + ch])    \
                          + (pre4[2][cr][192 + ch] + pre4[3][cr][192 + ch])) + gx4.w; \
                gx4 = pf4;                                                     \
                float cn = siga(fv) * cmy + siga(iv) * tanha(gv);              \
                float hn = siga(ov) * tanha(cn);                               \
                cmy = cn;                                                      \
                if (glmy == (TCUR)) { mgh = hn; mgc = cn; }                    \
                HWR[cr][ch] = hn;                                              \
            }                                                                  \
            __syncthreads();                                                   \
        }

        #pragma unroll 1
        for (int t = 0; t < TT; t += 2) {
            LSTEP(hA, hB, t,     t + 1)
            LSTEP(hB, hA, t + 1, (t + 2 < TT) ? t + 2 : TT - 1)
        }
        #undef LSTEP
    }

    if (comb) ghh[cr][ch] = mgh;
    __syncthreads();

    // ---- MLP head ----
    for (int p = tid; p < BT * 128; p += NTHR) {
        int r = p >> 7, j = p & 127;
        float acc = bl1[j];
        const float* wr = Wl1 + j * HH;
        #pragma unroll
        for (int k = 0; k < HH; ++k) acc = fmaf(ghh[r][k], wr[k], acc);
        l1sh[r][j] = tanha(acc);
    }
    __syncthreads();
    if (tid < BT * 4) {
        int r = tid >> 2, kk = tid & 3;
        float acc = bl2[kk];
        const float* wr = Wl2 + kk * 128;
        #pragma unroll
        for (int k = 0; k < 128; ++k) acc = fmaf(l1sh[r][k], wr[k], acc);
        out[(b0 + r) * 4 + kk] = acc;
    }
}

// 148 CTAs x 4 rows + 144 CTAs x 3 rows = 1024 (bid i, i+148 share an SM).
__global__ void __launch_bounds__(NTHR, 2) cond_enc_kernel(
    const int*   __restrict__ s1,   const int*   __restrict__ s2,
    const int*   __restrict__ len1, const int*   __restrict__ len2,
    const float* __restrict__ Whh1, const float* __restrict__ Whh2,
    const float* __restrict__ Wl1,  const float* __restrict__ bl1,
    const float* __restrict__ Wl2,  const float* __restrict__ bl2,
    float* __restrict__ out)
{
    __shared__ int   toksh[4][TT];
    __shared__ __align__(16) float hA[4][HP];
    __shared__ __align__(16) float hB[4][HP];
    __shared__ __align__(16) float pre4[4][4][GG];
    __shared__ float ghh[4][HH];
    __shared__ float l1sh[4][128];

    const int tid = threadIdx.x;
    if (blockIdx.x < 148) {
        run_lstm<4>(blockIdx.x * 4, tid, s1, s2, len1, len2, Whh1, Whh2,
                    Wl1, bl1, Wl2, bl2, out, toksh, hA, hB, pre4, ghh, l1sh);
    } else {
        run_lstm<3>(592 + (blockIdx.x - 148) * 3, tid, s1, s2, len1, len2, Whh1, Whh2,
                    Wl1, bl1, Wl2, bl2, out, toksh, hA, hB, pre4, ghh, l1sh);
    }
}

extern "C" void kernel_launch(void* const* d_in, const int* in_sizes, int n_in,
                              void* d_out, int out_size)
{
    const int*   s1   = (const int*)  d_in[0];
    const int*   s2   = (const int*)  d_in[1];
    const int*   len1 = (const int*)  d_in[2];
    const int*   len2 = (const int*)  d_in[3];
    // d_in[4], d_in[5] (s1_s, s2_s) unused by the reference model
    const float* emb  = (const float*)d_in[6];
    const float* Wih1 = (const float*)d_in[7];
    const float* Whh1 = (const float*)d_in[8];
    const float* bih1 = (const float*)d_in[9];
    const float* bhh1 = (const float*)d_in[10];
    const float* Wih2 = (const float*)d_in[11];
    const float* Whh2 = (const float*)d_in[12];
    const float* bih2 = (const float*)d_in[13];
    const float* bhh2 = (const float*)d_in[14];
    const float* Wl1  = (const float*)d_in[15];
    const float* bl1  = (const float*)d_in[16];
    const float* Wl2  = (const float*)d_in[17];
    const float* bl2  = (const float*)d_in[18];
    float* out = (float*)d_out;

    precompute_kernel<<<2 * VB, 256>>>(emb, Wih1, bih1, bhh1, Wih2, bih2, bhh2);
    cond_enc_kernel<<<292, NTHR>>>(s1, s2, len1, len2,
                                   Whh1, Whh2, Wl1, bl1, Wl2, bl2, out);
}

// round 10
// speedup vs baseline: 1.7079x; 1.7079x over previous
#include <cuda_runtime.h>

// Conditional encoding: 2-layer LSTM (B=1024, T=256, D=50, H=64) + MLP head.
// x@Wih^T+bias precomputed per vocab entry; tab[v][ch][{i,f,g,o}] so combine
// fetches gate-x with one LDG.128.
// Recurrence: 148 CTAs x 7 rows, ONE CTA per SM, 512 threads (full reg
// budget, no spills). Thread = gate PAIR x k-quarter; pre4 smem exchange;
// combine by 448 threads; 2 barriers/step.

#define BB   1024
#define TT   256
#define DD   50
#define HH   64
#define GG   256   // 4*H
#define VV   32004
#define BT   7     // batch rows per recurrent CTA
#define NCTA 148
#define NTHR 512
#define HP   72    // padded h row stride
#define VB   1001  // ceil(32004/32)

typedef unsigned long long u64;

__device__ float g_tab0[(long)VV * GG];   // layer-1 table, [v][ch][4] = i,f,g,o
__device__ float g_tab1[(long)VV * GG];   // layer-2 table

__device__ __forceinline__ u64 pk2(float a, float b) {
    u64 r; asm("mov.b64 %0, {%1, %2};" : "=l"(r) : "f"(a), "f"(b)); return r;
}
__device__ __forceinline__ u64 ffma2(u64 a, u64 b, u64 c) {
    u64 d; asm("fma.rn.f32x2 %0, %1, %2, %3;" : "=l"(d) : "l"(a), "l"(b), "l"(c)); return d;
}
__device__ __forceinline__ float pairsum(u64 a) {
    float x, y; asm("mov.b64 {%0, %1}, %2;" : "=f"(x), "=f"(y) : "l"(a)); return x + y;
}
__device__ __forceinline__ float tanha(float x) {
    float y; asm("tanh.approx.f32 %0, %1;" : "=f"(y) : "f"(x)); return y;
}
__device__ __forceinline__ float siga(float x) {
    return fmaf(0.5f, tanha(0.5f * x), 0.5f);
}

// staging remap: gate g -> bit7 = type>=2, bits[6:1] = channel, bit0 = type&1.
__device__ __forceinline__ int remap(int g) {
    return ((g >> 7) << 7) | ((g & 63) << 1) | ((g >> 6) & 1);
}

// ---------------- precompute: tab[v][ch][4] = {i,f,g,o} preacts ----------------
__global__ void __launch_bounds__(256) precompute_kernel(
    const float* __restrict__ emb,
    const float* __restrict__ WihA, const float* __restrict__ biA, const float* __restrict__ bhA,
    const float* __restrict__ WihB, const float* __restrict__ biB, const float* __restrict__ bhB)
{
    const int layer = blockIdx.x >= VB;
    const int vb    = layer ? blockIdx.x - VB : blockIdx.x;
    const float* Wih = layer ? WihB : WihA;
    const float* bi  = layer ? biB  : biA;
    const float* bh  = layer ? bhB  : bhA;
    float* tab = layer ? g_tab1 : g_tab0;

    __shared__ float xs[32][DD];
    __shared__ __align__(8) float wsT[25][GG];
    __shared__ __align__(8) float bsh[GG];

    const int tid = threadIdx.x;
    const int v0  = vb * 32;
    const int rm  = remap(tid);

    for (int idx = tid; idx < 32 * DD; idx += 256) {
        int v = idx / DD, k = idx - v * DD;
        int vg = v0 + v;
        xs[v][k] = (vg < VV) ? emb[(long)vg * DD + k] : 0.f;
    }
    bsh[rm] = bi[tid] + bh[tid];
    __syncthreads();

    const int gg = tid & 31;
    const int vq = tid >> 5;
    const int off0 = 2 * gg, off1 = 128 + 2 * gg;
    const int off2 = 2 * (gg + 32), off3 = 128 + 2 * (gg + 32);

    u64 acc[4][4];
    {
        u64 b0 = *(const u64*)&bsh[off0], b1 = *(const u64*)&bsh[off1];
        u64 b2 = *(const u64*)&bsh[off2], b3 = *(const u64*)&bsh[off3];
        #pragma unroll
        for (int v = 0; v < 4; ++v) {
            acc[v][0] = b0; acc[v][1] = b1; acc[v][2] = b2; acc[v][3] = b3;
        }
    }

    for (int kc = 0; kc < 2; ++kc) {
        __syncthreads();
        {
            const float* wp = Wih + (long)tid * DD + kc * 25;
            #pragma unroll
            for (int k = 0; k < 25; ++k) wsT[k][rm] = wp[k];
        }
        __syncthreads();
        #pragma unroll
        for (int k = 0; k < 25; ++k) {
            u64 w0 = *(const u64*)&wsT[k][off0];
            u64 w1 = *(const u64*)&wsT[k][off1];
            u64 w2 = *(const u64*)&wsT[k][off2];
            u64 w3 = *(const u64*)&wsT[k][off3];
            #pragma unroll
            for (int v = 0; v < 4; ++v) {
                float xv = xs[vq * 4 + v][kc * 25 + k];
                u64 xp = pk2(xv, xv);
                acc[v][0] = ffma2(w0, xp, acc[v][0]);
                acc[v][1] = ffma2(w1, xp, acc[v][1]);
                acc[v][2] = ffma2(w2, xp, acc[v][2]);
                acc[v][3] = ffma2(w3, xp, acc[v][3]);
            }
        }
    }

    #pragma unroll
    for (int v = 0; v < 4; ++v) {
        int vg = v0 + vq * 4 + v;
        if (vg < VV) {
            float* base = tab + (long)vg * GG;
            *(u64*)(base + 4 * gg)            = acc[v][0];
            *(u64*)(base + 4 * gg + 2)        = acc[v][1];
            *(u64*)(base + 4 * (gg + 32))     = acc[v][2];
            *(u64*)(base + 4 * (gg + 32) + 2) = acc[v][3];
        }
    }
}

// ---------------- recurrent kernel: 1 CTA/SM, 7 rows, 512 threads ----------------
__global__ void __launch_bounds__(NTHR, 1) cond_enc_kernel(
    const int*   __restrict__ s1,   const int*   __restrict__ s2,
    const int*   __restrict__ len1, const int*   __restrict__ len2,
    const float* __restrict__ Whh1, const float* __restrict__ Whh2,
    const float* __restrict__ Wl1,  const float* __restrict__ bl1,
    const float* __restrict__ Wl2,  const float* __restrict__ bl2,
    float* __restrict__ out)
{
    __shared__ int   toksh[BT][TT];                       // 7 KB
    __shared__ __align__(16) float hA[BT][HP];
    __shared__ __align__(16) float hB[BT][HP];
    __shared__ __align__(16) float pre4[4][BT][GG];       // 28 KB
    __shared__ float ghh[BT][HH];
    __shared__ float l1sh[BT][128];

    const int tid = threadIdx.x;
    const int b0  = blockIdx.x * BT;
    const int P   = tid & 127;           // gate pair: gates 2P, 2P+1
    const int kq  = tid >> 7;            // k quarter: h[16kq .. 16kq+15]
    const int cr  = tid >> 6;            // combine row (0..7)
    const int ch  = tid & 63;            // combine channel
    const bool comb = (cr < BT);         // 448 combine threads

    u64    wreg[16];                     // [gi*8+j]: gate 2P+gi, k-pair j
    float4 gx4, pf4;
    float  cmy = 0.f, mgh = 0.f, mgc = 0.f;
    int    glmy = -1;

    for (int phase = 0; phase < 2; ++phase) {
        const int*   sent = phase ? s2   : s1;
        const int*   slen = phase ? len2 : len1;
        const float* Whh  = phase ? Whh2 : Whh1;
        const float* tab  = phase ? g_tab1 : g_tab0;

        #pragma unroll
        for (int gi = 0; gi < 2; ++gi) {
            const float4* wp = (const float4*)(Whh + (long)(2 * P + gi) * HH + 16 * kq);
            #pragma unroll
            for (int j = 0; j < 4; ++j) {
                float4 w = wp[j];
                wreg[gi * 8 + 2 * j]     = pk2(w.x, w.y);
                wreg[gi * 8 + 2 * j + 1] = pk2(w.z, w.w);
            }
        }
        for (int idx = tid; idx < BT * TT; idx += NTHR) {
            int r = idx >> 8, t = idx & 255;
            int b = b0 + r; if (b > BB - 1) b = BB - 1;
            toksh[r][t] = sent[b * TT + t];
        }
        if (comb) {
            int b = b0 + cr; if (b > BB - 1) b = BB - 1;
            glmy = slen[b * HH + ch];
            cmy  = (phase == 0) ? 0.f : mgc;
            hA[cr][ch] = (phase == 0) ? 0.f : mgh;
        }
        __syncthreads();

        if (comb)
            gx4 = __ldg((const float4*)&tab[(long)toksh[cr][0] * GG + 4 * ch]);

        #define LSTEP(HRD, HWR, TCUR, TNX)                                     \
        {                                                                      \
            if (comb)                                                          \
                pf4 = __ldg((const float4*)&tab[(long)toksh[cr][(TNX)] * GG + 4 * ch]); \
            _Pragma("unroll")                                                  \
            for (int r = 0; r < BT; ++r) {                                     \
                const ulonglong2* hp = (const ulonglong2*)&HRD[r][16 * kq];    \
                ulonglong2 h0 = hp[0], h1 = hp[1], h2 = hp[2], h3 = hp[3];     \
                u64 a0 = 0ULL, a1 = 0ULL;                                      \
                a0 = ffma2(wreg[0], h0.x, a0); a1 = ffma2(wreg[8],  h0.x, a1); \
                a0 = ffma2(wreg[1], h0.y, a0); a1 = ffma2(wreg[9],  h0.y, a1); \
                a0 = ffma2(wreg[2], h1.x, a0); a1 = ffma2(wreg[10], h1.x, a1); \
                a0 = ffma2(wreg[3], h1.y, a0); a1 = ffma2(wreg[11], h1.y, a1); \
                a0 = ffma2(wreg[4], h2.x, a0); a1 = ffma2(wreg[12], h2.x, a1); \
                a0 = ffma2(wreg[5], h2.y, a0); a1 = ffma2(wreg[13], h2.y, a1); \
                a0 = ffma2(wreg[6], h3.x, a0); a1 = ffma2(wreg[14], h3.x, a1); \
                a0 = ffma2(wreg[7], h3.y, a0); a1 = ffma2(wreg[15], h3.y, a1); \
                float2 s;                                                      \
                s.x = pairsum(a0); s.y = pairsum(a1);                          \
                *(float2*)&pre4[kq][r][2 * P] = s;                             \
            }                                                                  \
            __syncthreads();                                                   \
            if (comb) {                                                        \
                float iv = ((pre4[0][cr][ch] + pre4[1][cr][ch])                \
                          + (pre4[2][cr][ch] + pre4[3][cr][ch])) + gx4.x;      \
                float fv = ((pre4[0][cr][64 + ch] + pre4[1][cr][64 + ch])      \
                          + (pre4[2][cr][64 + ch] + pre4[3][cr][64 + ch])) + gx4.y; \
                float gv = ((pre4[0][cr][128 + ch] + pre4[1][cr][128 + ch])    \
                          + (pre4[2][cr][128 + ch] + pre4[3][cr][128 + ch])) + gx4.z; \
                float ov = ((pre4[0][cr][192 + ch] + pre4[1][cr][192 + ch])    \
                          + (pre4[2][cr][192 + ch] + pre4[3][cr][192 + ch])) + gx4.w; \
                gx4 = pf4;                                                     \
                float cn = siga(fv) * cmy + siga(iv) * tanha(gv);              \
                float hn = siga(ov) * tanha(cn);                               \
                cmy = cn;                                                      \
                if (glmy == (TCUR)) { mgh = hn; mgc = cn; }                    \
                HWR[cr][ch] = hn;                                              \
            }                                                                  \
            __syncthreads();                                                   \
        }

        #pragma unroll 1
        for (int t = 0; t < TT; t += 2) {
            LSTEP(hA, hB, t,     t + 1)
            LSTEP(hB, hA, t + 1, (t + 2 < TT) ? t + 2 : TT - 1)
        }
        #undef LSTEP
    }

    if (comb) ghh[cr][ch] = mgh;
    __syncthreads();

    // ================= MLP head =================
    for (int p = tid; p < BT * 128; p += NTHR) {
        int r = p >> 7, j = p & 127;
        float acc = bl1[j];
        const float* wr = Wl1 + j * HH;
        #pragma unroll
        for (int k = 0; k < HH; ++k) acc = fmaf(ghh[r][k], wr[k], acc);
        l1sh[r][j] = tanha(acc);
    }
    __syncthreads();
    if (tid < BT * 4) {
        int r = tid >> 2, kk = tid & 3;
        int b = b0 + r;
        if (b < BB) {
            float acc = bl2[kk];
            const float* wr = Wl2 + kk * 128;
            #pragma unroll
            for (int k = 0; k < 128; ++k) acc = fmaf(l1sh[r][k], wr[k], acc);
            out[b * 4 + kk] = acc;
        }
    }
}

extern "C" void kernel_launch(void* const* d_in, const int* in_sizes, int n_in,
                              void* d_out, int out_size)
{
    const int*   s1   = (const int*)  d_in[0];
    const int*   s2   = (const int*)  d_in[1];
    const int*   len1 = (const int*)  d_in[2];
    const int*   len2 = (const int*)  d_in[3];
    // d_in[4], d_in[5] (s1_s, s2_s) unused by the reference model
    const float* emb  = (const float*)d_in[6];
    const float* Wih1 = (const float*)d_in[7];
    const float* Whh1 = (const float*)d_in[8];
    const float* bih1 = (const float*)d_in[9];
    const float* bhh1 = (const float*)d_in[10];
    const float* Wih2 = (const float*)d_in[11];
    const float* Whh2 = (const float*)d_in[12];
    const float* bih2 = (const float*)d_in[13];
    const float* bhh2 = (const float*)d_in[14];
    const float* Wl1  = (const float*)d_in[15];
    const float* bl1  = (const float*)d_in[16];
    const float* Wl2  = (const float*)d_in[17];
    const float* bl2  = (const float*)d_in[18];
    float* out = (float*)d_out;

    precompute_kernel<<<2 * VB, 256>>>(emb, Wih1, bih1, bhh1, Wih2, bih2, bhh2);
    cond_enc_kernel<<<NCTA, NTHR>>>(s1, s2, len1, len2,
                                    Whh1, Whh2, Wl1, bl1, Wl2, bl2, out);
}

// round 11
// speedup vs baseline: 1.9570x; 1.1458x over previous
#include <cuda_runtime.h>

// Conditional encoding: 2-layer LSTM (B=1024, T=256, D=50, H=64) + MLP head.
// x@Wih^T+bias precomputed per vocab entry; tab[v][ch][{i,f,g,o}].
// Recurrence: grid 292 = 148x4 + 144x3 rows, 256 thr, 2 CTAs/SM.
// Thread = CHANNEL x k-quarter: computes (i,f,g,o) partials of one channel ->
// float4 STS; combine reads 4x LDS.128 + packed f32x2 adds (lean tail).

#define BB   1024
#define TT   256
#define DD   50
#define HH   64
#define GG   256   // 4*H
#define VV   32004
#define NTHR 256
#define HP   72    // padded h row stride
#define VB   1001  // ceil(32004/32)

typedef unsigned long long u64;

__device__ float g_tab0[(long)VV * GG];   // layer-1 table, [v][ch][4] = i,f,g,o
__device__ float g_tab1[(long)VV * GG];   // layer-2 table

__device__ __forceinline__ u64 pk2(float a, float b) {
    u64 r; asm("mov.b64 %0, {%1, %2};" : "=l"(r) : "f"(a), "f"(b)); return r;
}
__device__ __forceinline__ u64 ffma2(u64 a, u64 b, u64 c) {
    u64 d; asm("fma.rn.f32x2 %0, %1, %2, %3;" : "=l"(d) : "l"(a), "l"(b), "l"(c)); return d;
}
__device__ __forceinline__ u64 addf2(u64 a, u64 b) {
    u64 d; asm("add.rn.f32x2 %0, %1, %2;" : "=l"(d) : "l"(a), "l"(b)); return d;
}
__device__ __forceinline__ float pairsum(u64 a) {
    float x, y; asm("mov.b64 {%0, %1}, %2;" : "=f"(x), "=f"(y) : "l"(a)); return x + y;
}
__device__ __forceinline__ void unpk(float& x, float& y, u64 a) {
    asm("mov.b64 {%0, %1}, %2;" : "=f"(x), "=f"(y) : "l"(a));
}
__device__ __forceinline__ float tanha(float x) {
    float y; asm("tanh.approx.f32 %0, %1;" : "=f"(y) : "f"(x)); return y;
}
__device__ __forceinline__ float siga(float x) {
    return fmaf(0.5f, tanha(0.5f * x), 0.5f);
}

// staging remap: gate g -> bit7 = type>=2, bits[6:1] = channel, bit0 = type&1.
__device__ __forceinline__ int remap(int g) {
    return ((g >> 7) << 7) | ((g & 63) << 1) | ((g >> 6) & 1);
}

// ---------------- precompute: tab[v][ch][4] = {i,f,g,o} preacts ----------------
__global__ void __launch_bounds__(256) precompute_kernel(
    const float* __restrict__ emb,
    const float* __restrict__ WihA, const float* __restrict__ biA, const float* __restrict__ bhA,
    const float* __restrict__ WihB, const float* __restrict__ biB, const float* __restrict__ bhB)
{
    const int layer = blockIdx.x >= VB;
    const int vb    = layer ? blockIdx.x - VB : blockIdx.x;
    const float* Wih = layer ? WihB : WihA;
    const float* bi  = layer ? biB  : biA;
    const float* bh  = layer ? bhB  : bhA;
    float* tab = layer ? g_tab1 : g_tab0;

    __shared__ float xs[32][DD];
    __shared__ __align__(8) float wsT[25][GG];
    __shared__ __align__(8) float bsh[GG];

    const int tid = threadIdx.x;
    const int v0  = vb * 32;
    const int rm  = remap(tid);

    for (int idx = tid; idx < 32 * DD; idx += 256) {
        int v = idx / DD, k = idx - v * DD;
        int vg = v0 + v;
        xs[v][k] = (vg < VV) ? emb[(long)vg * DD + k] : 0.f;
    }
    bsh[rm] = bi[tid] + bh[tid];
    __syncthreads();

    const int gg = tid & 31;
    const int vq = tid >> 5;
    const int off0 = 2 * gg, off1 = 128 + 2 * gg;
    const int off2 = 2 * (gg + 32), off3 = 128 + 2 * (gg + 32);

    u64 acc[4][4];
    {
        u64 b0 = *(const u64*)&bsh[off0], b1 = *(const u64*)&bsh[off1];
        u64 b2 = *(const u64*)&bsh[off2], b3 = *(const u64*)&bsh[off3];
        #pragma unroll
        for (int v = 0; v < 4; ++v) {
            acc[v][0] = b0; acc[v][1] = b1; acc[v][2] = b2; acc[v][3] = b3;
        }
    }

    for (int kc = 0; kc < 2; ++kc) {
        __syncthreads();
        {
            const float* wp = Wih + (long)tid * DD + kc * 25;
            #pragma unroll
            for (int k = 0; k < 25; ++k) wsT[k][rm] = wp[k];
        }
        __syncthreads();
        #pragma unroll
        for (int k = 0; k < 25; ++k) {
            u64 w0 = *(const u64*)&wsT[k][off0];
            u64 w1 = *(const u64*)&wsT[k][off1];
            u64 w2 = *(const u64*)&wsT[k][off2];
            u64 w3 = *(const u64*)&wsT[k][off3];
            #pragma unroll
            for (int v = 0; v < 4; ++v) {
                float xv = xs[vq * 4 + v][kc * 25 + k];
                u64 xp = pk2(xv, xv);
                acc[v][0] = ffma2(w0, xp, acc[v][0]);
                acc[v][1] = ffma2(w1, xp, acc[v][1]);
                acc[v][2] = ffma2(w2, xp, acc[v][2]);
                acc[v][3] = ffma2(w3, xp, acc[v][3]);
            }
        }
    }

    #pragma unroll
    for (int v = 0; v < 4; ++v) {
        int vg = v0 + vq * 4 + v;
        if (vg < VV) {
            float* base = tab + (long)vg * GG;
            *(u64*)(base + 4 * gg)            = acc[v][0];
            *(u64*)(base + 4 * gg + 2)        = acc[v][1];
            *(u64*)(base + 4 * (gg + 32))     = acc[v][2];
            *(u64*)(base + 4 * (gg + 32) + 2) = acc[v][3];
        }
    }
}

// ---------------- recurrent core (templated on rows per CTA) ----------------
template <int BT>
__device__ __forceinline__ void run_lstm(
    int b0, int tid,
    const int*   __restrict__ s1,   const int*   __restrict__ s2,
    const int*   __restrict__ len1, const int*   __restrict__ len2,
    const float* __restrict__ Whh1, const float* __restrict__ Whh2,
    const float* __restrict__ Wl1,  const float* __restrict__ bl1,
    const float* __restrict__ Wl2,  const float* __restrict__ bl2,
    float* __restrict__ out,
    int   (*toksh)[TT],
    float (*hA)[HP], float (*hB)[HP],
    float (*pre4)[4][GG],
    float (*ghh)[HH], float (*l1sh)[128])
{
    const int q  = tid & 63;             // channel: gates {q, 64+q, 128+q, 192+q}
    const int kq = tid >> 6;             // k quarter: h[16kq .. 16kq+15]
    const int cr = tid >> 6;             // combine row
    const int ch = tid & 63;             // combine channel
    const bool comb = (tid < BT * 64);

    u64        wreg[32];                 // [gi*8+j]: gate type gi of channel q
    ulonglong2 gx2, pf2;                 // packed (i,f),(g,o) gate-x
    float      cmy = 0.f, mgh = 0.f, mgc = 0.f;
    int        glmy = -1;

    for (int phase = 0; phase < 2; ++phase) {
        const int*   sent = phase ? s2   : s1;
        const int*   slen = phase ? len2 : len1;
        const float* Whh  = phase ? Whh2 : Whh1;
        const float* tab  = phase ? g_tab1 : g_tab0;

        #pragma unroll
        for (int gi = 0; gi < 4; ++gi) {
            const float4* wp = (const float4*)(Whh + (long)(gi * HH + q) * HH + 16 * kq);
            #pragma unroll
            for (int j = 0; j < 4; ++j) {
                float4 w = wp[j];
                wreg[gi * 8 + 2 * j]     = pk2(w.x, w.y);
                wreg[gi * 8 + 2 * j + 1] = pk2(w.z, w.w);
            }
        }
        for (int idx = tid; idx < BT * TT; idx += NTHR) {
            int r = idx >> 8, t = idx & 255;
            toksh[r][t] = sent[(b0 + r) * TT + t];
        }
        if (comb) {
            glmy = slen[(b0 + cr) * HH + ch];
            cmy  = (phase == 0) ? 0.f : mgc;
            hA[cr][ch] = (phase == 0) ? 0.f : mgh;
        }
        __syncthreads();

        if (comb)
            gx2 = __ldg((const ulonglong2*)&tab[(long)toksh[cr][0] * GG + 4 * ch]);

        #define LSTEP(HRD, HWR, TCUR, TNX)                                     \
        {                                                                      \
            if (comb)                                                          \
                pf2 = __ldg((const ulonglong2*)&tab[(long)toksh[cr][(TNX)] * GG + 4 * ch]); \
            _Pragma("unroll")                                                  \
            for (int r = 0; r < BT; ++r) {                                     \
                const ulonglong2* hp = (const ulonglong2*)&HRD[r][16 * kq];    \
                ulonglong2 h0 = hp[0], h1 = hp[1], h2 = hp[2], h3 = hp[3];     \
                u64 a0 = 0ULL, a1 = 0ULL, a2 = 0ULL, a3 = 0ULL;                \
                a0 = ffma2(wreg[0], h0.x, a0); a1 = ffma2(wreg[8],  h0.x, a1); \
                a2 = ffma2(wreg[16], h0.x, a2); a3 = ffma2(wreg[24], h0.x, a3);\
                a0 = ffma2(wreg[1], h0.y, a0); a1 = ffma2(wreg[9],  h0.y, a1); \
                a2 = ffma2(wreg[17], h0.y, a2); a3 = ffma2(wreg[25], h0.y, a3);\
                a0 = ffma2(wreg[2], h1.x, a0); a1 = ffma2(wreg[10], h1.x, a1); \
                a2 = ffma2(wreg[18], h1.x, a2); a3 = ffma2(wreg[26], h1.x, a3);\
                a0 = ffma2(wreg[3], h1.y, a0); a1 = ffma2(wreg[11], h1.y, a1); \
                a2 = ffma2(wreg[19], h1.y, a2); a3 = ffma2(wreg[27], h1.y, a3);\
                a0 = ffma2(wreg[4], h2.x, a0); a1 = ffma2(wreg[12], h2.x, a1); \
                a2 = ffma2(wreg[20], h2.x, a2); a3 = ffma2(wreg[28], h2.x, a3);\
                a0 = ffma2(wreg[5], h2.y, a0); a1 = ffma2(wreg[13], h2.y, a1); \
                a2 = ffma2(wreg[21], h2.y, a2); a3 = ffma2(wreg[29], h2.y, a3);\
                a0 = ffma2(wreg[6], h3.x, a0); a1 = ffma2(wreg[14], h3.x, a1); \
                a2 = ffma2(wreg[22], h3.x, a2); a3 = ffma2(wreg[30], h3.x, a3);\
                a0 = ffma2(wreg[7], h3.y, a0); a1 = ffma2(wreg[15], h3.y, a1); \
                a2 = ffma2(wreg[23], h3.y, a2); a3 = ffma2(wreg[31], h3.y, a3);\
                float4 s;                                                      \
                s.x = pairsum(a0); s.y = pairsum(a1);                          \
                s.z = pairsum(a2); s.w = pairsum(a3);                          \
                *(float4*)&pre4[kq][r][4 * q] = s;   /* (i,f,g,o) of ch=q */   \
            }                                                                  \
            __syncthreads();                                                   \
            if (comb) {                                                        \
                const ulonglong2* p0 = (const ulonglong2*)&pre4[0][cr][4 * ch];\
                const ulonglong2* p1 = (const ulonglong2*)&pre4[1][cr][4 * ch];\
                const ulonglong2* p2 = (const ulonglong2*)&pre4[2][cr][4 * ch];\
                const ulonglong2* p3 = (const ulonglong2*)&pre4[3][cr][4 * ch];\
                ulonglong2 v0 = *p0, v1 = *p1, v2 = *p2, v3 = *p3;             \
                u64 tif = addf2(addf2(v0.x, v1.x), addf2(v2.x, v3.x));         \
                u64 tgo = addf2(addf2(v0.y, v1.y), addf2(v2.y, v3.y));         \
                tif = addf2(tif, gx2.x);                                       \
                tgo = addf2(tgo, gx2.y);                                       \
                gx2 = pf2;                                                     \
                float iv, fv, gv, ov;                                          \
                unpk(iv, fv, tif);                                             \
                unpk(gv, ov, tgo);                                             \
                float cn = siga(fv) * cmy + siga(iv) * tanha(gv);              \
                float hn = siga(ov) * tanha(cn);                               \
                cmy = cn;                                                      \
                if (glmy == (TCUR)) { mgh = hn; mgc = cn; }                    \
                HWR[cr][ch] = hn;                                              \
            }                                                                  \
            __syncthreads();                                                   \
        }

        #pragma unroll 1
        for (int t = 0; t < TT; t += 2) {
            LSTEP(hA, hB, t,     t + 1)
            LSTEP(hB, hA, t + 1, (t + 2 < TT) ? t + 2 : TT - 1)
        }
        #undef LSTEP
    }

    if (comb) ghh[cr][ch] = mgh;
    __syncthreads();

    // ---- MLP head ----
    for (int p = tid; p < BT * 128; p += NTHR) {
        int r = p >> 7, j = p & 127;
        float acc = bl1[j];
        const float* wr = Wl1 + j * HH;
        #pragma unroll
        for (int k = 0; k < HH; ++k) acc = fmaf(ghh[r][k], wr[k], acc);
        l1sh[r][j] = tanha(acc);
    }
    __syncthreads();
    if (tid < BT * 4) {
        int r = tid >> 2, kk = tid & 3;
        float acc = bl2[kk];
        const float* wr = Wl2 + kk * 128;
        #pragma unroll
        for (int k = 0; k < 128; ++k) acc = fmaf(l1sh[r][k], wr[k], acc);
        out[(b0 + r) * 4 + kk] = acc;
    }
}

// 148 CTAs x 4 rows + 144 CTAs x 3 rows = 1024 (bid i, i+148 share an SM).
__global__ void __launch_bounds__(NTHR, 2) cond_enc_kernel(
    const int*   __restrict__ s1,   const int*   __restrict__ s2,
    const int*   __restrict__ len1, const int*   __restrict__ len2,
    const float* __restrict__ Whh1, const float* __restrict__ Whh2,
    const float* __restrict__ Wl1,  const float* __restrict__ bl1,
    const float* __restrict__ Wl2,  const float* __restrict__ bl2,
    float* __restrict__ out)
{
    __shared__ int   toksh[4][TT];
    __shared__ __align__(16) float hA[4][HP];
    __shared__ __align__(16) float hB[4][HP];
    __shared__ __align__(16) float pre4[4][4][GG];
    __shared__ float ghh[4][HH];
    __shared__ float l1sh[4][128];

    const int tid = threadIdx.x;
    if (blockIdx.x < 148) {
        run_lstm<4>(blockIdx.x * 4, tid, s1, s2, len1, len2, Whh1, Whh2,
                    Wl1, bl1, Wl2, bl2, out, toksh, hA, hB, pre4, ghh, l1sh);
    } else {
        run_lstm<3>(592 + (blockIdx.x - 148) * 3, tid, s1, s2, len1, len2, Whh1, Whh2,
                    Wl1, bl1, Wl2, bl2, out, toksh, hA, hB, pre4, ghh, l1sh);
    }
}

extern "C" void kernel_launch(void* const* d_in, const int* in_sizes, int n_in,
                              void* d_out, int out_size)
{
    const int*   s1   = (const int*)  d_in[0];
    const int*   s2   = (const int*)  d_in[1];
    const int*   len1 = (const int*)  d_in[2];
    const int*   len2 = (const int*)  d_in[3];
    // d_in[4], d_in[5] (s1_s, s2_s) unused by the reference model
    const float* emb  = (const float*)d_in[6];
    const float* Wih1 = (const float*)d_in[7];
    const float* Whh1 = (const float*)d_in[8];
    const float* bih1 = (const float*)d_in[9];
    const float* bhh1 = (const float*)d_in[10];
    const float* Wih2 = (const float*)d_in[11];
    const float* Whh2 = (const float*)d_in[12];
    const float* bih2 = (const float*)d_in[13];
    const float* bhh2 = (const float*)d_in[14];
    const float* Wl1  = (const float*)d_in[15];
    const float* bl1  = (const float*)d_in[16];
    const float* Wl2  = (const float*)d_in[17];
    const float* bl2  = (const float*)d_in[18];
    float* out = (float*)d_out;

    precompute_kernel<<<2 * VB, 256>>>(emb, Wih1, bih1, bhh1, Wih2, bih2, bhh2);
    cond_enc_kernel<<<292, NTHR>>>(s1, s2, len1, len2,
                                   Whh1, Whh2, Wl1, bl1, Wl2, bl2, out);
}